// round 4
// baseline (speedup 1.0000x reference)
#include <cuda_runtime.h>
#include <cstdint>

// RowSoftmax over edges:
//   et  = exp(leaky_relu(attr, 0.01))
//   out = et / segment_sum(et, row)
//
// NOTE: reference requests jnp.int64 but JAX x64 is disabled -> edge_index is
// int32 on device. d_in[0] is (2, E) int32; row = first E entries.

#define N_NODES 1000000

// 4 MB scratch: segment sums (L2-resident during the hot passes).
__device__ float g_rowsum[N_NODES];

__global__ void zero_rowsum_kernel() {
    int i = blockIdx.x * blockDim.x + threadIdx.x;
    if (i < N_NODES) g_rowsum[i] = 0.0f;
}

__device__ __forceinline__ float et_of(float a) {
    float lr = a > 0.0f ? a : 0.01f * a;
    return expf(lr);
}

// Pass A: compute et, write to out, scatter-add into g_rowsum. 4 edges/thread.
__global__ void scatter_kernel(const int* __restrict__ row,
                               const float* __restrict__ attr,
                               float* __restrict__ out,
                               int E) {
    int t = blockIdx.x * blockDim.x + threadIdx.x;
    int e = t * 4;
    if (e + 3 < E) {
        float4 a = *reinterpret_cast<const float4*>(attr + e);
        int4   r = *reinterpret_cast<const int4*>(row + e);
        float e0 = et_of(a.x);
        float e1 = et_of(a.y);
        float e2 = et_of(a.z);
        float e3 = et_of(a.w);
        *reinterpret_cast<float4*>(out + e) = make_float4(e0, e1, e2, e3);
        atomicAdd(&g_rowsum[r.x], e0);
        atomicAdd(&g_rowsum[r.y], e1);
        atomicAdd(&g_rowsum[r.z], e2);
        atomicAdd(&g_rowsum[r.w], e3);
    } else {
        for (int k = e; k < E; k++) {
            float ek = et_of(attr[k]);
            out[k] = ek;
            atomicAdd(&g_rowsum[row[k]], ek);
        }
    }
}

// Invert sums in place: rinv = 1 / rowsum.
__global__ void recip_kernel() {
    int i = blockIdx.x * blockDim.x + threadIdx.x;
    if (i < N_NODES) g_rowsum[i] = 1.0f / g_rowsum[i];
}

// Pass B: out[e] *= rinv[row[e]]  (rinv gather hits L2).
__global__ void normalize_kernel(const int* __restrict__ row,
                                 float* __restrict__ out,
                                 int E) {
    int t = blockIdx.x * blockDim.x + threadIdx.x;
    int e = t * 4;
    if (e + 3 < E) {
        float4 v = *reinterpret_cast<const float4*>(out + e);
        int4   r = *reinterpret_cast<const int4*>(row + e);
        float s0 = g_rowsum[r.x];
        float s1 = g_rowsum[r.y];
        float s2 = g_rowsum[r.z];
        float s3 = g_rowsum[r.w];
        v.x *= s0; v.y *= s1; v.z *= s2; v.w *= s3;
        *reinterpret_cast<float4*>(out + e) = v;
    } else {
        for (int k = e; k < E; k++) {
            out[k] *= g_rowsum[row[k]];
        }
    }
}

extern "C" void kernel_launch(void* const* d_in, const int* in_sizes, int n_in,
                              void* d_out, int out_size) {
    const int*   row  = (const int*)d_in[0];   // first E of (2,E) int32
    const float* attr = (const float*)d_in[1];
    float*       out  = (float*)d_out;
    int E = in_sizes[1];

    const int T = 256;
    int nblk = (N_NODES + T - 1) / T;
    zero_rowsum_kernel<<<nblk, T>>>();

    int e4 = (E + 3) / 4;
    int eblk = (e4 + T - 1) / T;
    scatter_kernel<<<eblk, T>>>(row, attr, out, E);

    recip_kernel<<<nblk, T>>>();

    normalize_kernel<<<eblk, T>>>(row, out, E);
}

// round 7
// speedup vs baseline: 1.3346x; 1.3346x over previous
#include <cuda_runtime.h>
#include <cstdint>

// RowSoftmax over edges:
//   et  = exp(leaky_relu(attr, 0.01))
//   out = et / segment_sum(et, row)
//
// edge_index is int32 on device (JAX x64 disabled). d_in[0] = (2,E) int32,
// row = first E entries.
//
// Perf model (B300): normalize is L1tex wavefront-bound (2.07 cyc/wf divergent
// gather replays), scatter is REDG spread-addr bound (1.29 cyc/lane). Both
// kernels run at per-SM LSU floors, not DRAM. This round: maximize MLP and
// strip non-LSU work.

#define N_NODES 1000000

__device__ float g_rowsum[N_NODES];  // 4 MB, L2-resident during hot passes

__global__ void zero_rowsum_kernel() {
    int i = blockIdx.x * blockDim.x + threadIdx.x;
    // N_NODES = 1,000,000 divisible by 4
    if (i < N_NODES / 4) {
        reinterpret_cast<float4*>(g_rowsum)[i] = make_float4(0.f, 0.f, 0.f, 0.f);
    }
}

__device__ __forceinline__ float et_of(float a) {
    float lr = a > 0.0f ? a : 0.01f * a;
    return __expf(lr);
}

// Pass A: et = exp(lrelu(attr)); out = et; g_rowsum[row] += et. 8 edges/thread.
__global__ void scatter_kernel(const int* __restrict__ row,
                               const float* __restrict__ attr,
                               float* __restrict__ out,
                               int E) {
    int t = blockIdx.x * blockDim.x + threadIdx.x;
    int e = t * 8;
    if (e + 7 < E) {
        // Front-batch all global loads for MLP
        float4 a0 = *reinterpret_cast<const float4*>(attr + e);
        float4 a1 = *reinterpret_cast<const float4*>(attr + e + 4);
        int4   r0 = *reinterpret_cast<const int4*>(row + e);
        int4   r1 = *reinterpret_cast<const int4*>(row + e + 4);

        float e0 = et_of(a0.x), e1 = et_of(a0.y), e2 = et_of(a0.z), e3 = et_of(a0.w);
        float e4 = et_of(a1.x), e5 = et_of(a1.y), e6 = et_of(a1.z), e7 = et_of(a1.w);

        *reinterpret_cast<float4*>(out + e)     = make_float4(e0, e1, e2, e3);
        *reinterpret_cast<float4*>(out + e + 4) = make_float4(e4, e5, e6, e7);

        atomicAdd(&g_rowsum[r0.x], e0);
        atomicAdd(&g_rowsum[r0.y], e1);
        atomicAdd(&g_rowsum[r0.z], e2);
        atomicAdd(&g_rowsum[r0.w], e3);
        atomicAdd(&g_rowsum[r1.x], e4);
        atomicAdd(&g_rowsum[r1.y], e5);
        atomicAdd(&g_rowsum[r1.z], e6);
        atomicAdd(&g_rowsum[r1.w], e7);
    } else {
        for (int k = e; k < E; k++) {
            float lr = attr[k] > 0.0f ? attr[k] : 0.01f * attr[k];
            float ek = expf(lr);
            out[k] = ek;
            atomicAdd(&g_rowsum[row[k]], ek);
        }
    }
}

// Invert sums in place.
__global__ void recip_kernel() {
    int i = blockIdx.x * blockDim.x + threadIdx.x;
    if (i < N_NODES) g_rowsum[i] = 1.0f / g_rowsum[i];
}

// Pass B: out[e] *= rinv[row[e]]. 8 edges/thread, front-batched loads.
__global__ void normalize_kernel(const int* __restrict__ row,
                                 float* __restrict__ out,
                                 int E) {
    int t = blockIdx.x * blockDim.x + threadIdx.x;
    int e = t * 8;
    if (e + 7 < E) {
        int4   r0 = *reinterpret_cast<const int4*>(row + e);
        int4   r1 = *reinterpret_cast<const int4*>(row + e + 4);
        float4 v0 = *reinterpret_cast<const float4*>(out + e);
        float4 v1 = *reinterpret_cast<const float4*>(out + e + 4);

        float s0 = g_rowsum[r0.x];
        float s1 = g_rowsum[r0.y];
        float s2 = g_rowsum[r0.z];
        float s3 = g_rowsum[r0.w];
        float s4 = g_rowsum[r1.x];
        float s5 = g_rowsum[r1.y];
        float s6 = g_rowsum[r1.z];
        float s7 = g_rowsum[r1.w];

        v0.x *= s0; v0.y *= s1; v0.z *= s2; v0.w *= s3;
        v1.x *= s4; v1.y *= s5; v1.z *= s6; v1.w *= s7;

        *reinterpret_cast<float4*>(out + e)     = v0;
        *reinterpret_cast<float4*>(out + e + 4) = v1;
    } else {
        for (int k = e; k < E; k++) {
            out[k] *= g_rowsum[row[k]];
        }
    }
}

extern "C" void kernel_launch(void* const* d_in, const int* in_sizes, int n_in,
                              void* d_out, int out_size) {
    const int*   row  = (const int*)d_in[0];   // first E of (2,E) int32
    const float* attr = (const float*)d_in[1];
    float*       out  = (float*)d_out;
    int E = in_sizes[1];

    const int T = 256;
    zero_rowsum_kernel<<<(N_NODES / 4 + T - 1) / T, T>>>();

    int e8 = (E + 7) / 8;
    int eblk = (e8 + T - 1) / T;
    scatter_kernel<<<eblk, T>>>(row, attr, out, E);

    recip_kernel<<<(N_NODES + T - 1) / T, T>>>();

    normalize_kernel<<<eblk, T>>>(row, out, E);
}